// round 14
// baseline (speedup 1.0000x reference)
#include <cuda_runtime.h>
#include <cuda_fp16.h>
#include <cstdint>

#define NN 100000
#define EE 1200000

// ---------------- device scratch (static, allocation-free) ----------------
__device__ int   g_cnt[2 * NN];
__device__ int   g_rp_pos[NN + 1];
__device__ int   g_rp_neg[NN + 1];
__device__ int   g_cur_pos[NN];
__device__ int   g_cur_neg[NN];
__device__ float g_inv_pos[NN];
__device__ float g_inv_neg[NN];
__device__ int   g_src_pos[EE];
__device__ int   g_src_neg[EE];
__device__ int   g_bsum_pos[128];
__device__ int   g_bsum_neg[128];
__device__ __align__(16) __half g_U0h[NN * 128];   // [yp(64) | yn(64)] fp16 (gathered by layer0)
__device__ __align__(16) __half g_U0sh[NN * 128];  // [sp(64) | sn(64)] fp16 (self terms)
__device__ __align__(16) __half g_Zh[NN * 128];    // z after layer 0 (fp16)
__device__ __align__(16) __half g_Z2h[NN * 128];   // z after layer 1 (fp16)
__device__ __align__(16) __half g_AGGPh[NN * 128]; // [Apos[0:64] | Aneg[64:128]] fp16
__device__ __align__(16) __half g_AGGNh[NN * 128]; // [Apos[64:128] | Aneg[0:64]] fp16

// packed bf16 weights: 4 layer stacks (24576 B each) then gemm0 (2 x 32768 B) = 163840 B
__device__ __align__(16) uint32_t g_WB_h[40960];
__device__ __align__(16) uint32_t g_WB_l[40960];

// ---------------- helpers ----------------
__device__ __forceinline__ uint32_t smem_u32(const void* p) {
    uint32_t a;
    asm("{ .reg .u64 t; cvta.to.shared.u64 t, %1; cvt.u32.u64 %0, t; }" : "=r"(a) : "l"(p));
    return a;
}
__device__ __forceinline__ uint32_t swz(uint32_t o) { return o ^ ((o >> 3) & 0x70); }

__device__ __forceinline__ void split_pair(float2 v, uint32_t& h2, uint32_t& l2) {
    asm("cvt.rn.bf16x2.f32 %0, %1, %2;" : "=r"(h2) : "f"(v.y), "f"(v.x));
    float lx = v.x - __uint_as_float(h2 << 16);
    float ly = v.y - __uint_as_float(h2 & 0xffff0000u);
    asm("cvt.rn.bf16x2.f32 %0, %1, %2;" : "=r"(l2) : "f"(ly), "f"(lx));
}

__device__ __forceinline__ void ldsm4(uint32_t* r, uint32_t addr) {
    asm volatile("ldmatrix.sync.aligned.m8n8.x4.shared.b16 {%0,%1,%2,%3}, [%4];"
                 : "=r"(r[0]), "=r"(r[1]), "=r"(r[2]), "=r"(r[3]) : "r"(addr));
}

__device__ __forceinline__ void mma16816(float* c, const uint32_t* a, const uint32_t* b) {
    asm volatile(
        "mma.sync.aligned.m16n8k16.row.col.f32.bf16.bf16.f32 "
        "{%0,%1,%2,%3}, {%4,%5,%6,%7}, {%8,%9}, {%0,%1,%2,%3};"
        : "+f"(c[0]), "+f"(c[1]), "+f"(c[2]), "+f"(c[3])
        : "r"(a[0]), "r"(a[1]), "r"(a[2]), "r"(a[3]), "r"(b[0]), "r"(b[1]));
}

__device__ __forceinline__ void acc_h8(float4& a0, float4& a1, uint4 raw) {
    float2 f0 = __half22float2(*(const __half2*)&raw.x);
    float2 f1 = __half22float2(*(const __half2*)&raw.y);
    float2 f2 = __half22float2(*(const __half2*)&raw.z);
    float2 f3 = __half22float2(*(const __half2*)&raw.w);
    a0.x += f0.x; a0.y += f0.y; a0.z += f1.x; a0.w += f1.y;
    a1.x += f2.x; a1.y += f2.y; a1.z += f3.x; a1.w += f3.y;
}

__device__ __forceinline__ void unpack_h8(uint4 raw, float4& f0, float4& f1) {
    float2 a = __half22float2(*(const __half2*)&raw.x);
    float2 b = __half22float2(*(const __half2*)&raw.y);
    float2 c = __half22float2(*(const __half2*)&raw.z);
    float2 d = __half22float2(*(const __half2*)&raw.w);
    f0 = make_float4(a.x, a.y, b.x, b.y);
    f1 = make_float4(c.x, c.y, d.x, d.y);
}

__device__ __forceinline__ uint4 pack_h8(float4 a0, float4 a1) {
    __half2 h0 = __floats2half2_rn(a0.x, a0.y), h1 = __floats2half2_rn(a0.z, a0.w);
    __half2 h2 = __floats2half2_rn(a1.x, a1.y), h3 = __floats2half2_rn(a1.z, a1.w);
    return make_uint4(*(uint32_t*)&h0, *(uint32_t*)&h1, *(uint32_t*)&h2, *(uint32_t*)&h3);
}

// ---------------- CSR build ----------------
__global__ void zero_cnt_k() {
    int i = blockIdx.x * blockDim.x + threadIdx.x;
    if (i < 2 * NN) g_cnt[i] = 0;
}
__global__ void hist2_k(const int* __restrict__ pdst, const int* __restrict__ ndst) {
    for (int i = blockIdx.x * blockDim.x + threadIdx.x; i < 2 * EE; i += gridDim.x * blockDim.x) {
        if (i < EE) atomicAdd(&g_cnt[pdst[i]], 1);
        else        atomicAdd(&g_cnt[NN + ndst[i - EE]], 1);
    }
}
__global__ void scan1m_k() {
    int which = blockIdx.y;
    const int* cnt = g_cnt + which * NN;
    int* incl = which ? g_rp_neg : g_rp_pos;
    int* bsum = which ? g_bsum_neg : g_bsum_pos;
    __shared__ int sh[1024];
    int i = blockIdx.x * 1024 + threadIdx.x;
    int v = (i < NN) ? cnt[i] : 0;
    sh[threadIdx.x] = v;
    __syncthreads();
    for (int off = 1; off < 1024; off <<= 1) {
        int t = (threadIdx.x >= off) ? sh[threadIdx.x - off] : 0;
        __syncthreads();
        sh[threadIdx.x] += t;
        __syncthreads();
    }
    if (i < NN) incl[i] = sh[threadIdx.x];
    if (threadIdx.x == 1023) bsum[blockIdx.x] = sh[1023];
}
__global__ void scan2m_k(int nb) {
    int which = blockIdx.x;
    int* bsum = which ? g_bsum_neg : g_bsum_pos;
    __shared__ int sh[128];
    int v = (threadIdx.x < nb) ? bsum[threadIdx.x] : 0;
    sh[threadIdx.x] = v;
    __syncthreads();
    for (int off = 1; off < 128; off <<= 1) {
        int t = (threadIdx.x >= off) ? sh[threadIdx.x - off] : 0;
        __syncthreads();
        sh[threadIdx.x] += t;
        __syncthreads();
    }
    if (threadIdx.x < nb) bsum[threadIdx.x] = sh[threadIdx.x] - v;
}
__global__ void scan3m_k() {
    int which = blockIdx.y;
    const int* cnt = g_cnt + which * NN;
    int* rp = which ? g_rp_neg : g_rp_pos;
    int* cur = which ? g_cur_neg : g_cur_pos;
    float* inv = which ? g_inv_neg : g_inv_pos;
    const int* bsum = which ? g_bsum_neg : g_bsum_pos;
    int i = blockIdx.x * blockDim.x + threadIdx.x;
    if (i < NN) {
        int inc = rp[i] + bsum[i >> 10];
        int c = cnt[i];
        int ex = inc - c;
        rp[i] = ex;
        cur[i] = ex;
        inv[i] = 1.0f / (float)(c > 0 ? c : 1);
    }
    if (i == 0) rp[NN] = EE;
}
__global__ void scatter2_k(const int* __restrict__ ps, const int* __restrict__ pd,
                           const int* __restrict__ ns, const int* __restrict__ nd) {
    for (int i = blockIdx.x * blockDim.x + threadIdx.x; i < 2 * EE; i += gridDim.x * blockDim.x) {
        if (i < EE) {
            int d = pd[i];
            int p = atomicAdd(&g_cur_pos[d], 1);
            g_src_pos[p] = ps[i];
        } else {
            int d = nd[i - EE];
            int p = atomicAdd(&g_cur_neg[d], 1);
            g_src_neg[p] = ns[i - EE];
        }
    }
}

// ---------------- weight prep: fp32 -> bf16 hi/lo, [n][k] rows, SW128-swizzled 64-k chunks ----------------
__global__ void prep_w_k(const float* __restrict__ Wl_pos, const float* __restrict__ Wr_pos,
                         const float* __restrict__ Wl_neg, const float* __restrict__ Wr_neg,
                         const float* __restrict__ Wp_l, const float* __restrict__ Wn_l,
                         const float* __restrict__ Wp_r, const float* __restrict__ Wn_r) {
    int idx = blockIdx.x * blockDim.x + threadIdx.x;
    float2 v;
    uint32_t off;
    if (idx < 24576) {
        int stack = idx / 6144, rem = idx % 6144;
        int n = rem / 96, kp = rem % 96, k = kp * 2;
        int l = stack >> 1, h = stack & 1;
        const float* WL = h ? Wl_neg : Wl_pos;  // [2][128][64]
        const float* WR = h ? Wr_neg : Wr_pos;  // [2][64][64]
        if (k < 128) {
            v.x = WL[l * 8192 + k * 64 + n];
            v.y = WL[l * 8192 + (k + 1) * 64 + n];
        } else {
            int kk = k - 128;
            v.x = WR[l * 4096 + kk * 64 + n];
            v.y = WR[l * 4096 + (kk + 1) * 64 + n];
        }
        off = (uint32_t)stack * 24576u + (uint32_t)(k >> 6) * 8192u + swz((uint32_t)n * 128u + (k & 63) * 2u);
    } else if (idx < 24576 + 16384) {
        int j = idx - 24576;
        int colsel = j / 8192, rem = j % 8192;
        int n = rem / 64, kp = rem % 64, k = kp * 2;
        const float* W = (n < 64) ? (colsel ? Wp_r : Wp_l) : (colsel ? Wn_r : Wn_l);
        int nn = n & 63;
        v.x = W[k * 64 + nn];
        v.y = W[(k + 1) * 64 + nn];
        off = 98304u + (uint32_t)colsel * 32768u + (uint32_t)(k >> 6) * 16384u + swz((uint32_t)n * 128u + (k & 63) * 2u);
    } else {
        return;
    }
    uint32_t h2, l2;
    split_pair(v, h2, l2);
    g_WB_h[off >> 2] = h2;
    g_WB_l[off >> 2] = l2;
}

// ---------------- layer GEMM, both halves in one launch (blockIdx.y = half); all-fp16 A ----------------
__global__ void __launch_bounds__(256) mma_layer_dual_k(
    const __half* __restrict__ A0a, const __half* __restrict__ A0b,
    const __half* __restrict__ A1h, int bBaseA,
    const float* __restrict__ biasA, const float* __restrict__ biasB,
    float* __restrict__ outF, __half* __restrict__ outH, int outHalf)
{
    __shared__ uint32_t sAh[4096], sAl[4096];
    __shared__ uint32_t sBh[2048], sBl[2048];
    int tid = threadIdx.x, wid = tid >> 5, lane = tid & 31;
    int v0 = blockIdx.x * 128;
    int h = blockIdx.y;
    const __half* A0 = h ? A0b : A0a;
    const float* bias = h ? biasB : biasA;
    int bBase = bBaseA + h * 24576;
    int zOff = h * 64, outOff = h * 64;

    uint32_t aHb = smem_u32(sAh), aLb = smem_u32(sAl);
    uint32_t bHb = smem_u32(sBh), bLb = smem_u32(sBl);

    int lr = lane & 7, g = lane >> 3;
    int arow = wid * 16 + lr + (g & 1) * 8;
    uint32_t aPreH = aHb + arow * 128, aPreL = aLb + arow * 128;
    uint32_t xmA = (uint32_t)(arow & 7) * 16;
    uint32_t kbA = (uint32_t)(g >> 1) * 16;
    int brow = lr + (g >> 1) * 8;
    uint32_t xmB = (uint32_t)lr * 16;
    uint32_t kbB = (uint32_t)(g & 1) * 16;

    float acc[8][4] = {};

    for (int kc = 0; kc < 3; kc++) {
        {
            const uint4* bh = (const uint4*)((const char*)g_WB_h + bBase + kc * 8192);
            const uint4* bl = (const uint4*)((const char*)g_WB_l + bBase + kc * 8192);
            for (int i = tid; i < 512; i += 256) {
                ((uint4*)sBh)[i] = bh[i];
                ((uint4*)sBl)[i] = bl[i];
            }
        }
        for (int idx = tid; idx < 4096; idx += 256) {
            int r = idx >> 5, kp = idx & 31;
            float2 v = make_float2(0.f, 0.f);
            if (v0 + r < NN) {
                const __half* src = (kc == 2) ? (A1h + (size_t)(v0 + r) * 128 + zOff + kp * 2)
                                              : (A0 + (size_t)(v0 + r) * 128 + kc * 64 + kp * 2);
                v = __half22float2(*(const __half2*)src);
            }
            uint32_t h2, l2;
            split_pair(v, h2, l2);
            uint32_t o = swz((uint32_t)r * 128u + (uint32_t)kp * 4u);
            *(uint32_t*)((char*)sAh + o) = h2;
            *(uint32_t*)((char*)sAl + o) = l2;
        }
        __syncthreads();

#pragma unroll
        for (int ks = 0; ks < 4; ks++) {
            uint32_t kb = ks * 32;
            uint32_t ah[4], al[4];
            ldsm4(ah, aPreH + ((kb + kbA) ^ xmA));
            ldsm4(al, aPreL + ((kb + kbA) ^ xmA));
#pragma unroll
            for (int nt2 = 0; nt2 < 4; nt2++) {
                int n = nt2 * 16 + brow;
                uint32_t bo = (uint32_t)n * 128 + ((kb + kbB) ^ xmB);
                uint32_t bh4[4], bl4[4];
                ldsm4(bh4, bHb + bo);
                ldsm4(bl4, bLb + bo);
                mma16816(acc[nt2 * 2],     ah, bh4);
                mma16816(acc[nt2 * 2 + 1], ah, bh4 + 2);
                mma16816(acc[nt2 * 2],     al, bh4);
                mma16816(acc[nt2 * 2 + 1], al, bh4 + 2);
                mma16816(acc[nt2 * 2],     ah, bl4);
                mma16816(acc[nt2 * 2 + 1], ah, bl4 + 2);
            }
        }
        __syncthreads();
    }

    int r0 = v0 + wid * 16 + (lane >> 2);
    int cb = (lane & 3) * 2;
#pragma unroll
    for (int j = 0; j < 8; j++) {
        int col = j * 8 + cb;
        float bx = bias[col], by = bias[col + 1];
        float ox = tanhf(acc[j][0] + bx), oy = tanhf(acc[j][1] + by);
        float px = tanhf(acc[j][2] + bx), py = tanhf(acc[j][3] + by);
        if (outHalf) {
            if (r0 < NN)     *(__half2*)(outH + (size_t)r0 * 128 + outOff + col)       = __floats2half2_rn(ox, oy);
            if (r0 + 8 < NN) *(__half2*)(outH + (size_t)(r0 + 8) * 128 + outOff + col) = __floats2half2_rn(px, py);
        } else {
            if (r0 < NN)     *(float2*)(outF + (size_t)r0 * 128 + outOff + col)       = make_float2(ox, oy);
            if (r0 + 8 < NN) *(float2*)(outF + (size_t)(r0 + 8) * 128 + outOff + col) = make_float2(px, py);
        }
    }
}

// ---------------- fused layer-0 GEMM: stage X once, both 64-col halves; blockIdx.y = colsel; fp16 out ----------------
__global__ void __launch_bounds__(256) mma_gemm0_dual_k(
    const float* __restrict__ X,
    __half* __restrict__ outL, __half* __restrict__ outR)
{
    __shared__ uint32_t sAh[4096], sAl[4096];
    __shared__ uint32_t sBh[2048], sBl[2048];
    int tid = threadIdx.x, wid = tid >> 5, lane = tid & 31;
    int v0 = blockIdx.x * 128;
    int colsel = blockIdx.y;                  // 0 = left weights -> U0h, 1 = right -> U0sh
    int bBase0 = 98304 + colsel * 32768;
    __half* outB = colsel ? outR : outL;

    uint32_t aHb = smem_u32(sAh), aLb = smem_u32(sAl);
    uint32_t bHb = smem_u32(sBh), bLb = smem_u32(sBl);

    int lr = lane & 7, g = lane >> 3;
    int arow = wid * 16 + lr + (g & 1) * 8;
    uint32_t aPreH = aHb + arow * 128, aPreL = aLb + arow * 128;
    uint32_t xmA = (uint32_t)(arow & 7) * 16;
    uint32_t kbA = (uint32_t)(g >> 1) * 16;
    int brow = lr + (g >> 1) * 8;
    uint32_t xmB = (uint32_t)lr * 16;
    uint32_t kbB = (uint32_t)(g & 1) * 16;

    float acc[2][8][4] = {};

    for (int kc = 0; kc < 2; kc++) {
        for (int idx = tid; idx < 4096; idx += 256) {
            int r = idx >> 5, kp = idx & 31;
            float2 v = make_float2(0.f, 0.f);
            if (v0 + r < NN) v = *(const float2*)(X + (size_t)(v0 + r) * 128 + kc * 64 + kp * 2);
            uint32_t h2, l2;
            split_pair(v, h2, l2);
            uint32_t o = swz((uint32_t)r * 128u + (uint32_t)kp * 4u);
            *(uint32_t*)((char*)sAh + o) = h2;
            *(uint32_t*)((char*)sAl + o) = l2;
        }
        __syncthreads();

        for (int h = 0; h < 2; h++) {
            {
                const uint4* bh = (const uint4*)((const char*)g_WB_h + bBase0 + h * 8192 + kc * 16384);
                const uint4* bl = (const uint4*)((const char*)g_WB_l + bBase0 + h * 8192 + kc * 16384);
                for (int i = tid; i < 512; i += 256) {
                    ((uint4*)sBh)[i] = bh[i];
                    ((uint4*)sBl)[i] = bl[i];
                }
            }
            __syncthreads();
#pragma unroll
            for (int ks = 0; ks < 4; ks++) {
                uint32_t kb = ks * 32;
                uint32_t ah[4], al[4];
                ldsm4(ah, aPreH + ((kb + kbA) ^ xmA));
                ldsm4(al, aPreL + ((kb + kbA) ^ xmA));
#pragma unroll
                for (int nt2 = 0; nt2 < 4; nt2++) {
                    int n = nt2 * 16 + brow;
                    uint32_t bo = (uint32_t)n * 128 + ((kb + kbB) ^ xmB);
                    uint32_t bh4[4], bl4[4];
                    ldsm4(bh4, bHb + bo);
                    ldsm4(bl4, bLb + bo);
                    mma16816(acc[h][nt2 * 2],     ah, bh4);
                    mma16816(acc[h][nt2 * 2 + 1], ah, bh4 + 2);
                    mma16816(acc[h][nt2 * 2],     al, bh4);
                    mma16816(acc[h][nt2 * 2 + 1], al, bh4 + 2);
                    mma16816(acc[h][nt2 * 2],     ah, bl4);
                    mma16816(acc[h][nt2 * 2 + 1], ah, bl4 + 2);
                }
            }
            __syncthreads();
        }
    }

    int r0 = v0 + wid * 16 + (lane >> 2);
    int cb = (lane & 3) * 2;
#pragma unroll
    for (int h = 0; h < 2; h++) {
        int outOff = h * 64;
#pragma unroll
        for (int j = 0; j < 8; j++) {
            int col = j * 8 + cb;
            if (r0 < NN)
                *(__half2*)(outB + (size_t)r0 * 128 + outOff + col) =
                    __floats2half2_rn(acc[h][j][0], acc[h][j][1]);
            if (r0 + 8 < NN)
                *(__half2*)(outB + (size_t)(r0 + 8) * 128 + outOff + col) =
                    __floats2half2_rn(acc[h][j][2], acc[h][j][3]);
        }
    }
}

// ---------------- Layer 0: quarter-warp-per-node (8 lanes) fp16 mean-gather + self + bias + tanh ----------------
__global__ void layer0_k(const float* __restrict__ bp, const float* __restrict__ bn) {
    int t = blockIdx.x * blockDim.x + threadIdx.x;
    int v = t >> 3;
    int lane = t & 7;
    if (v >= NN) return;
    int c8 = lane * 8;
    float4 aP0 = make_float4(0.f, 0.f, 0.f, 0.f), aP1 = make_float4(0.f, 0.f, 0.f, 0.f);
    float4 aN0 = make_float4(0.f, 0.f, 0.f, 0.f), aN1 = make_float4(0.f, 0.f, 0.f, 0.f);
    int b = g_rp_pos[v], e = g_rp_pos[v + 1];
#pragma unroll 4
    for (int i = b; i < e; i++) {
        int s = g_src_pos[i];
        uint4 raw = *(const uint4*)(g_U0h + (size_t)s * 128 + c8);
        acc_h8(aP0, aP1, raw);
    }
    b = g_rp_neg[v]; e = g_rp_neg[v + 1];
#pragma unroll 4
    for (int i = b; i < e; i++) {
        int s = g_src_neg[i];
        uint4 raw = *(const uint4*)(g_U0h + (size_t)s * 128 + 64 + c8);
        acc_h8(aN0, aN1, raw);
    }
    float ipv = g_inv_pos[v], inv = g_inv_neg[v];
    float4 sp0, sp1, sn0, sn1;
    unpack_h8(*(const uint4*)(g_U0sh + (size_t)v * 128 + c8), sp0, sp1);
    unpack_h8(*(const uint4*)(g_U0sh + (size_t)v * 128 + 64 + c8), sn0, sn1);
    float4 b1a = *(const float4*)(bp + c8), b1b = *(const float4*)(bp + c8 + 4);
    float4 b2a = *(const float4*)(bn + c8), b2b = *(const float4*)(bn + c8 + 4);
    float4 zp0, zp1, zn0, zn1;
    zp0.x = tanhf(aP0.x * ipv + sp0.x + b1a.x); zp0.y = tanhf(aP0.y * ipv + sp0.y + b1a.y);
    zp0.z = tanhf(aP0.z * ipv + sp0.z + b1a.z); zp0.w = tanhf(aP0.w * ipv + sp0.w + b1a.w);
    zp1.x = tanhf(aP1.x * ipv + sp1.x + b1b.x); zp1.y = tanhf(aP1.y * ipv + sp1.y + b1b.y);
    zp1.z = tanhf(aP1.z * ipv + sp1.z + b1b.z); zp1.w = tanhf(aP1.w * ipv + sp1.w + b1b.w);
    zn0.x = tanhf(aN0.x * inv + sn0.x + b2a.x); zn0.y = tanhf(aN0.y * inv + sn0.y + b2a.y);
    zn0.z = tanhf(aN0.z * inv + sn0.z + b2a.z); zn0.w = tanhf(aN0.w * inv + sn0.w + b2a.w);
    zn1.x = tanhf(aN1.x * inv + sn1.x + b2b.x); zn1.y = tanhf(aN1.y * inv + sn1.y + b2b.y);
    zn1.z = tanhf(aN1.z * inv + sn1.z + b2b.z); zn1.w = tanhf(aN1.w * inv + sn1.w + b2b.w);
    *(uint4*)(g_Zh + (size_t)v * 128 + c8)      = pack_h8(zp0, zp1);
    *(uint4*)(g_Zh + (size_t)v * 128 + 64 + c8) = pack_h8(zn0, zn1);
}

// ---------------- Layer aggregation: quarter-warp-per-node (8 lanes), permuted fp16 output ----------------
__global__ void agg_k(int zsel) {
    const __half* Z = zsel ? g_Z2h : g_Zh;
    int t = blockIdx.x * blockDim.x + threadIdx.x;
    int v = t >> 3;
    int lane = t & 7;
    if (v >= NN) return;
    int c16 = lane * 16;
    float4 aP0 = make_float4(0.f, 0.f, 0.f, 0.f), aP1 = make_float4(0.f, 0.f, 0.f, 0.f);
    float4 aP2 = make_float4(0.f, 0.f, 0.f, 0.f), aP3 = make_float4(0.f, 0.f, 0.f, 0.f);
    float4 aN0 = make_float4(0.f, 0.f, 0.f, 0.f), aN1 = make_float4(0.f, 0.f, 0.f, 0.f);
    float4 aN2 = make_float4(0.f, 0.f, 0.f, 0.f), aN3 = make_float4(0.f, 0.f, 0.f, 0.f);
    int b = g_rp_pos[v], e = g_rp_pos[v + 1];
#pragma unroll 2
    for (int i = b; i < e; i++) {
        int s = g_src_pos[i];
        const __half* row = Z + (size_t)s * 128 + c16;
        uint4 r0 = *(const uint4*)(row);
        uint4 r1 = *(const uint4*)(row + 8);
        acc_h8(aP0, aP1, r0);
        acc_h8(aP2, aP3, r1);
    }
    b = g_rp_neg[v]; e = g_rp_neg[v + 1];
#pragma unroll 2
    for (int i = b; i < e; i++) {
        int s = g_src_neg[i];
        const __half* row = Z + (size_t)s * 128 + c16;
        uint4 r0 = *(const uint4*)(row);
        uint4 r1 = *(const uint4*)(row + 8);
        acc_h8(aN0, aN1, r0);
        acc_h8(aN2, aN3, r1);
    }
    float ipv = g_inv_pos[v], inv = g_inv_neg[v];
    aP0.x *= ipv; aP0.y *= ipv; aP0.z *= ipv; aP0.w *= ipv;
    aP1.x *= ipv; aP1.y *= ipv; aP1.z *= ipv; aP1.w *= ipv;
    aP2.x *= ipv; aP2.y *= ipv; aP2.z *= ipv; aP2.w *= ipv;
    aP3.x *= ipv; aP3.y *= ipv; aP3.z *= ipv; aP3.w *= ipv;
    aN0.x *= inv; aN0.y *= inv; aN0.z *= inv; aN0.w *= inv;
    aN1.x *= inv; aN1.y *= inv; aN1.z *= inv; aN1.w *= inv;
    aN2.x *= inv; aN2.y *= inv; aN2.z *= inv; aN2.w *= inv;
    aN3.x *= inv; aN3.y *= inv; aN3.z *= inv; aN3.w *= inv;
    uint4 pP0 = pack_h8(aP0, aP1), pP1 = pack_h8(aP2, aP3);
    uint4 pN0 = pack_h8(aN0, aN1), pN1 = pack_h8(aN2, aN3);
    if (lane < 4) {
        // cols [0,64): Apos -> AGGP[c16], Aneg -> AGGN[64+c16]
        *(uint4*)(g_AGGPh + (size_t)v * 128 + c16)     = pP0;
        *(uint4*)(g_AGGPh + (size_t)v * 128 + c16 + 8) = pP1;
        *(uint4*)(g_AGGNh + (size_t)v * 128 + 64 + c16)     = pN0;
        *(uint4*)(g_AGGNh + (size_t)v * 128 + 64 + c16 + 8) = pN1;
    } else {
        // cols [64,128): Aneg -> AGGP[c16], Apos -> AGGN[c16-64]
        *(uint4*)(g_AGGPh + (size_t)v * 128 + c16)     = pN0;
        *(uint4*)(g_AGGPh + (size_t)v * 128 + c16 + 8) = pN1;
        *(uint4*)(g_AGGNh + (size_t)v * 128 + c16 - 64)     = pP0;
        *(uint4*)(g_AGGNh + (size_t)v * 128 + c16 - 64 + 8) = pP1;
    }
}

// ---------------- host launcher (single stream, capture-safe) ----------------
extern "C" void kernel_launch(void* const* d_in, const int* in_sizes, int n_in,
                              void* d_out, int out_size) {
    const float* x = (const float*)d_in[0];
    const int* pe = (const int*)d_in[1];   // int32 (JAX x64 disabled)
    const int* ne = (const int*)d_in[2];
    const float* Wp_l = (const float*)d_in[3];
    const float* Wp_r = (const float*)d_in[4];
    const float* bp = (const float*)d_in[5];
    const float* Wn_l = (const float*)d_in[6];
    const float* Wn_r = (const float*)d_in[7];
    const float* bn = (const float*)d_in[8];
    const float* Wl_pos = (const float*)d_in[9];
    const float* Wr_pos = (const float*)d_in[10];
    const float* b_pos = (const float*)d_in[11];
    const float* Wl_neg = (const float*)d_in[12];
    const float* Wr_neg = (const float*)d_in[13];
    const float* b_neg = (const float*)d_in[14];
    float* out = (float*)d_out;

    __half *dU0h, *dU0sh, *dZh, *dZ2h, *dAGGPh, *dAGGNh;
    cudaGetSymbolAddress((void**)&dU0h, g_U0h);
    cudaGetSymbolAddress((void**)&dU0sh, g_U0sh);
    cudaGetSymbolAddress((void**)&dZh, g_Zh);
    cudaGetSymbolAddress((void**)&dZ2h, g_Z2h);
    cudaGetSymbolAddress((void**)&dAGGPh, g_AGGPh);
    cudaGetSymbolAddress((void**)&dAGGNh, g_AGGNh);

    // --- weight prep ---
    prep_w_k<<<160, 256>>>(Wl_pos, Wr_pos, Wl_neg, Wr_neg, Wp_l, Wn_l, Wp_r, Wn_r);

    // --- CSR build ---
    zero_cnt_k<<<(2 * NN + 255) / 256, 256>>>();
    hist2_k<<<2048, 256>>>(pe + EE, ne + EE);
    const int NB = (NN + 1023) / 1024;
    { dim3 grd(NB, 2); scan1m_k<<<grd, 1024>>>(); }
    scan2m_k<<<2, 128>>>(NB);
    { dim3 grd((NN + 255) / 256, 2); scan3m_k<<<grd, 256>>>(); }
    scatter2_k<<<2048, 256>>>(pe, pe + EE, ne, ne + EE);

    const int NBT = (NN + 127) / 128;      // 782
    const int NBQ = (NN * 8 + 255) / 256;  // 3125 (quarter-warp per node)

    // --- layer 0 ---
    { dim3 grd(NBT, 2); mma_gemm0_dual_k<<<grd, 256>>>(x, dU0h, dU0sh); }
    layer0_k<<<NBQ, 256>>>(bp, bn);

    // --- layer 1 ---
    agg_k<<<NBQ, 256>>>(0);
    { dim3 grd(NBT, 2); mma_layer_dual_k<<<grd, 256>>>(dAGGPh, dAGGNh, dZh, 0, b_pos, b_neg, nullptr, dZ2h, 1); }

    // --- layer 2 ---
    agg_k<<<NBQ, 256>>>(1);
    { dim3 grd(NBT, 2); mma_layer_dual_k<<<grd, 256>>>(dAGGPh, dAGGNh, dZ2h, 2 * 24576, b_pos + 64, b_neg + 64, out, nullptr, 0); }
}

// round 15
// speedup vs baseline: 1.0674x; 1.0674x over previous
#include <cuda_runtime.h>
#include <cuda_fp16.h>
#include <cstdint>

#define NN 100000
#define EE 1200000

// ---------------- device scratch (static, allocation-free) ----------------
__device__ int   g_cnt[2 * NN];
__device__ int   g_rp_pos[NN + 1];
__device__ int   g_rp_neg[NN + 1];
__device__ int   g_cur_pos[NN];
__device__ int   g_cur_neg[NN];
__device__ float g_inv_pos[NN];
__device__ float g_inv_neg[NN];
__device__ int   g_src_pos[EE];
__device__ int   g_src_neg[EE];
__device__ int   g_bsum_pos[128];
__device__ int   g_bsum_neg[128];
__device__ __align__(16) __half g_U0h[NN * 128];   // [yp(64) | yn(64)] fp16 (gathered by layer0)
__device__ __align__(16) __half g_U0sh[NN * 128];  // [sp(64) | sn(64)] fp16 (self terms)
__device__ __align__(16) __half g_Zh[NN * 128];    // z after layer 0 (fp16)
__device__ __align__(16) __half g_Z2h[NN * 128];   // z after layer 1 (fp16)
__device__ __align__(16) __half g_AGGPh[NN * 128]; // [Apos[0:64] | Aneg[64:128]] fp16
__device__ __align__(16) __half g_AGGNh[NN * 128]; // [Apos[64:128] | Aneg[0:64]] fp16

// packed bf16 weights: 4 layer stacks (24576 B each) then gemm0 (2 x 32768 B) = 163840 B
__device__ __align__(16) uint32_t g_WB_h[40960];
__device__ __align__(16) uint32_t g_WB_l[40960];

// ---------------- helpers ----------------
__device__ __forceinline__ uint32_t smem_u32(const void* p) {
    uint32_t a;
    asm("{ .reg .u64 t; cvta.to.shared.u64 t, %1; cvt.u32.u64 %0, t; }" : "=r"(a) : "l"(p));
    return a;
}
__device__ __forceinline__ uint32_t swz(uint32_t o) { return o ^ ((o >> 3) & 0x70); }

__device__ __forceinline__ void split_pair(float2 v, uint32_t& h2, uint32_t& l2) {
    asm("cvt.rn.bf16x2.f32 %0, %1, %2;" : "=r"(h2) : "f"(v.y), "f"(v.x));
    float lx = v.x - __uint_as_float(h2 << 16);
    float ly = v.y - __uint_as_float(h2 & 0xffff0000u);
    asm("cvt.rn.bf16x2.f32 %0, %1, %2;" : "=r"(l2) : "f"(ly), "f"(lx));
}

__device__ __forceinline__ void ldsm4(uint32_t* r, uint32_t addr) {
    asm volatile("ldmatrix.sync.aligned.m8n8.x4.shared.b16 {%0,%1,%2,%3}, [%4];"
                 : "=r"(r[0]), "=r"(r[1]), "=r"(r[2]), "=r"(r[3]) : "r"(addr));
}

__device__ __forceinline__ void mma16816(float* c, const uint32_t* a, const uint32_t* b) {
    asm volatile(
        "mma.sync.aligned.m16n8k16.row.col.f32.bf16.bf16.f32 "
        "{%0,%1,%2,%3}, {%4,%5,%6,%7}, {%8,%9}, {%0,%1,%2,%3};"
        : "+f"(c[0]), "+f"(c[1]), "+f"(c[2]), "+f"(c[3])
        : "r"(a[0]), "r"(a[1]), "r"(a[2]), "r"(a[3]), "r"(b[0]), "r"(b[1]));
}

__device__ __forceinline__ void acc_h8(float4& a0, float4& a1, uint4 raw) {
    float2 f0 = __half22float2(*(const __half2*)&raw.x);
    float2 f1 = __half22float2(*(const __half2*)&raw.y);
    float2 f2 = __half22float2(*(const __half2*)&raw.z);
    float2 f3 = __half22float2(*(const __half2*)&raw.w);
    a0.x += f0.x; a0.y += f0.y; a0.z += f1.x; a0.w += f1.y;
    a1.x += f2.x; a1.y += f2.y; a1.z += f3.x; a1.w += f3.y;
}

__device__ __forceinline__ void unpack_h8(uint4 raw, float4& f0, float4& f1) {
    float2 a = __half22float2(*(const __half2*)&raw.x);
    float2 b = __half22float2(*(const __half2*)&raw.y);
    float2 c = __half22float2(*(const __half2*)&raw.z);
    float2 d = __half22float2(*(const __half2*)&raw.w);
    f0 = make_float4(a.x, a.y, b.x, b.y);
    f1 = make_float4(c.x, c.y, d.x, d.y);
}

__device__ __forceinline__ uint4 pack_h8(float4 a0, float4 a1) {
    __half2 h0 = __floats2half2_rn(a0.x, a0.y), h1 = __floats2half2_rn(a0.z, a0.w);
    __half2 h2 = __floats2half2_rn(a1.x, a1.y), h3 = __floats2half2_rn(a1.z, a1.w);
    return make_uint4(*(uint32_t*)&h0, *(uint32_t*)&h1, *(uint32_t*)&h2, *(uint32_t*)&h3);
}

// ---------------- CSR build ----------------
__global__ void zero_cnt_k() {
    int i = blockIdx.x * blockDim.x + threadIdx.x;
    if (i < 2 * NN) g_cnt[i] = 0;
}
__global__ void hist2_k(const int* __restrict__ pdst, const int* __restrict__ ndst) {
    for (int i = blockIdx.x * blockDim.x + threadIdx.x; i < 2 * EE; i += gridDim.x * blockDim.x) {
        if (i < EE) atomicAdd(&g_cnt[pdst[i]], 1);
        else        atomicAdd(&g_cnt[NN + ndst[i - EE]], 1);
    }
}
__global__ void scan1m_k() {
    int which = blockIdx.y;
    const int* cnt = g_cnt + which * NN;
    int* incl = which ? g_rp_neg : g_rp_pos;
    int* bsum = which ? g_bsum_neg : g_bsum_pos;
    __shared__ int sh[1024];
    int i = blockIdx.x * 1024 + threadIdx.x;
    int v = (i < NN) ? cnt[i] : 0;
    sh[threadIdx.x] = v;
    __syncthreads();
    for (int off = 1; off < 1024; off <<= 1) {
        int t = (threadIdx.x >= off) ? sh[threadIdx.x - off] : 0;
        __syncthreads();
        sh[threadIdx.x] += t;
        __syncthreads();
    }
    if (i < NN) incl[i] = sh[threadIdx.x];
    if (threadIdx.x == 1023) bsum[blockIdx.x] = sh[1023];
}
__global__ void scan2m_k(int nb) {
    int which = blockIdx.x;
    int* bsum = which ? g_bsum_neg : g_bsum_pos;
    __shared__ int sh[128];
    int v = (threadIdx.x < nb) ? bsum[threadIdx.x] : 0;
    sh[threadIdx.x] = v;
    __syncthreads();
    for (int off = 1; off < 128; off <<= 1) {
        int t = (threadIdx.x >= off) ? sh[threadIdx.x - off] : 0;
        __syncthreads();
        sh[threadIdx.x] += t;
        __syncthreads();
    }
    if (threadIdx.x < nb) bsum[threadIdx.x] = sh[threadIdx.x] - v;
}
__global__ void scan3m_k() {
    int which = blockIdx.y;
    const int* cnt = g_cnt + which * NN;
    int* rp = which ? g_rp_neg : g_rp_pos;
    int* cur = which ? g_cur_neg : g_cur_pos;
    float* inv = which ? g_inv_neg : g_inv_pos;
    const int* bsum = which ? g_bsum_neg : g_bsum_pos;
    int i = blockIdx.x * blockDim.x + threadIdx.x;
    if (i < NN) {
        int inc = rp[i] + bsum[i >> 10];
        int c = cnt[i];
        int ex = inc - c;
        rp[i] = ex;
        cur[i] = ex;
        inv[i] = 1.0f / (float)(c > 0 ? c : 1);
    }
    if (i == 0) rp[NN] = EE;
}
__global__ void scatter2_k(const int* __restrict__ ps, const int* __restrict__ pd,
                           const int* __restrict__ ns, const int* __restrict__ nd) {
    for (int i = blockIdx.x * blockDim.x + threadIdx.x; i < 2 * EE; i += gridDim.x * blockDim.x) {
        if (i < EE) {
            int d = pd[i];
            int p = atomicAdd(&g_cur_pos[d], 1);
            g_src_pos[p] = ps[i];
        } else {
            int d = nd[i - EE];
            int p = atomicAdd(&g_cur_neg[d], 1);
            g_src_neg[p] = ns[i - EE];
        }
    }
}

// ---------------- weight prep: fp32 -> bf16 hi/lo, [n][k] rows, SW128-swizzled 64-k chunks ----------------
__global__ void prep_w_k(const float* __restrict__ Wl_pos, const float* __restrict__ Wr_pos,
                         const float* __restrict__ Wl_neg, const float* __restrict__ Wr_neg,
                         const float* __restrict__ Wp_l, const float* __restrict__ Wn_l,
                         const float* __restrict__ Wp_r, const float* __restrict__ Wn_r) {
    int idx = blockIdx.x * blockDim.x + threadIdx.x;
    float2 v;
    uint32_t off;
    if (idx < 24576) {
        int stack = idx / 6144, rem = idx % 6144;
        int n = rem / 96, kp = rem % 96, k = kp * 2;
        int l = stack >> 1, h = stack & 1;
        const float* WL = h ? Wl_neg : Wl_pos;  // [2][128][64]
        const float* WR = h ? Wr_neg : Wr_pos;  // [2][64][64]
        if (k < 128) {
            v.x = WL[l * 8192 + k * 64 + n];
            v.y = WL[l * 8192 + (k + 1) * 64 + n];
        } else {
            int kk = k - 128;
            v.x = WR[l * 4096 + kk * 64 + n];
            v.y = WR[l * 4096 + (kk + 1) * 64 + n];
        }
        off = (uint32_t)stack * 24576u + (uint32_t)(k >> 6) * 8192u + swz((uint32_t)n * 128u + (k & 63) * 2u);
    } else if (idx < 24576 + 16384) {
        int j = idx - 24576;
        int colsel = j / 8192, rem = j % 8192;
        int n = rem / 64, kp = rem % 64, k = kp * 2;
        const float* W = (n < 64) ? (colsel ? Wp_r : Wp_l) : (colsel ? Wn_r : Wn_l);
        int nn = n & 63;
        v.x = W[k * 64 + nn];
        v.y = W[(k + 1) * 64 + nn];
        off = 98304u + (uint32_t)colsel * 32768u + (uint32_t)(k >> 6) * 16384u + swz((uint32_t)n * 128u + (k & 63) * 2u);
    } else {
        return;
    }
    uint32_t h2, l2;
    split_pair(v, h2, l2);
    g_WB_h[off >> 2] = h2;
    g_WB_l[off >> 2] = l2;
}

// ---------------- layer GEMM, both halves in one launch (blockIdx.y = half); all-fp16 A ----------------
__global__ void __launch_bounds__(256) mma_layer_dual_k(
    const __half* __restrict__ A0a, const __half* __restrict__ A0b,
    const __half* __restrict__ A1h, int bBaseA,
    const float* __restrict__ biasA, const float* __restrict__ biasB,
    float* __restrict__ outF, __half* __restrict__ outH, int outHalf)
{
    __shared__ uint32_t sAh[4096], sAl[4096];
    __shared__ uint32_t sBh[2048], sBl[2048];
    int tid = threadIdx.x, wid = tid >> 5, lane = tid & 31;
    int v0 = blockIdx.x * 128;
    int h = blockIdx.y;
    const __half* A0 = h ? A0b : A0a;
    const float* bias = h ? biasB : biasA;
    int bBase = bBaseA + h * 24576;
    int zOff = h * 64, outOff = h * 64;

    uint32_t aHb = smem_u32(sAh), aLb = smem_u32(sAl);
    uint32_t bHb = smem_u32(sBh), bLb = smem_u32(sBl);

    int lr = lane & 7, g = lane >> 3;
    int arow = wid * 16 + lr + (g & 1) * 8;
    uint32_t aPreH = aHb + arow * 128, aPreL = aLb + arow * 128;
    uint32_t xmA = (uint32_t)(arow & 7) * 16;
    uint32_t kbA = (uint32_t)(g >> 1) * 16;
    int brow = lr + (g >> 1) * 8;
    uint32_t xmB = (uint32_t)lr * 16;
    uint32_t kbB = (uint32_t)(g & 1) * 16;

    float acc[8][4] = {};

    for (int kc = 0; kc < 3; kc++) {
        {
            const uint4* bh = (const uint4*)((const char*)g_WB_h + bBase + kc * 8192);
            const uint4* bl = (const uint4*)((const char*)g_WB_l + bBase + kc * 8192);
            for (int i = tid; i < 512; i += 256) {
                ((uint4*)sBh)[i] = bh[i];
                ((uint4*)sBl)[i] = bl[i];
            }
        }
        for (int idx = tid; idx < 4096; idx += 256) {
            int r = idx >> 5, kp = idx & 31;
            float2 v = make_float2(0.f, 0.f);
            if (v0 + r < NN) {
                const __half* src = (kc == 2) ? (A1h + (size_t)(v0 + r) * 128 + zOff + kp * 2)
                                              : (A0 + (size_t)(v0 + r) * 128 + kc * 64 + kp * 2);
                v = __half22float2(*(const __half2*)src);
            }
            uint32_t h2, l2;
            split_pair(v, h2, l2);
            uint32_t o = swz((uint32_t)r * 128u + (uint32_t)kp * 4u);
            *(uint32_t*)((char*)sAh + o) = h2;
            *(uint32_t*)((char*)sAl + o) = l2;
        }
        __syncthreads();

#pragma unroll
        for (int ks = 0; ks < 4; ks++) {
            uint32_t kb = ks * 32;
            uint32_t ah[4], al[4];
            ldsm4(ah, aPreH + ((kb + kbA) ^ xmA));
            ldsm4(al, aPreL + ((kb + kbA) ^ xmA));
#pragma unroll
            for (int nt2 = 0; nt2 < 4; nt2++) {
                int n = nt2 * 16 + brow;
                uint32_t bo = (uint32_t)n * 128 + ((kb + kbB) ^ xmB);
                uint32_t bh4[4], bl4[4];
                ldsm4(bh4, bHb + bo);
                ldsm4(bl4, bLb + bo);
                mma16816(acc[nt2 * 2],     ah, bh4);
                mma16816(acc[nt2 * 2 + 1], ah, bh4 + 2);
                mma16816(acc[nt2 * 2],     al, bh4);
                mma16816(acc[nt2 * 2 + 1], al, bh4 + 2);
                mma16816(acc[nt2 * 2],     ah, bl4);
                mma16816(acc[nt2 * 2 + 1], ah, bl4 + 2);
            }
        }
        __syncthreads();
    }

    int r0 = v0 + wid * 16 + (lane >> 2);
    int cb = (lane & 3) * 2;
#pragma unroll
    for (int j = 0; j < 8; j++) {
        int col = j * 8 + cb;
        float bx = bias[col], by = bias[col + 1];
        float ox = tanhf(acc[j][0] + bx), oy = tanhf(acc[j][1] + by);
        float px = tanhf(acc[j][2] + bx), py = tanhf(acc[j][3] + by);
        if (outHalf) {
            if (r0 < NN)     *(__half2*)(outH + (size_t)r0 * 128 + outOff + col)       = __floats2half2_rn(ox, oy);
            if (r0 + 8 < NN) *(__half2*)(outH + (size_t)(r0 + 8) * 128 + outOff + col) = __floats2half2_rn(px, py);
        } else {
            if (r0 < NN)     *(float2*)(outF + (size_t)r0 * 128 + outOff + col)       = make_float2(ox, oy);
            if (r0 + 8 < NN) *(float2*)(outF + (size_t)(r0 + 8) * 128 + outOff + col) = make_float2(px, py);
        }
    }
}

// ---------------- fused layer-0 GEMM: stage X once, both 64-col halves; blockIdx.y = colsel; fp16 out ----------------
__global__ void __launch_bounds__(256) mma_gemm0_dual_k(
    const float* __restrict__ X,
    __half* __restrict__ outL, __half* __restrict__ outR)
{
    __shared__ uint32_t sAh[4096], sAl[4096];
    __shared__ uint32_t sBh[2048], sBl[2048];
    int tid = threadIdx.x, wid = tid >> 5, lane = tid & 31;
    int v0 = blockIdx.x * 128;
    int colsel = blockIdx.y;                  // 0 = left weights -> U0h, 1 = right -> U0sh
    int bBase0 = 98304 + colsel * 32768;
    __half* outB = colsel ? outR : outL;

    uint32_t aHb = smem_u32(sAh), aLb = smem_u32(sAl);
    uint32_t bHb = smem_u32(sBh), bLb = smem_u32(sBl);

    int lr = lane & 7, g = lane >> 3;
    int arow = wid * 16 + lr + (g & 1) * 8;
    uint32_t aPreH = aHb + arow * 128, aPreL = aLb + arow * 128;
    uint32_t xmA = (uint32_t)(arow & 7) * 16;
    uint32_t kbA = (uint32_t)(g >> 1) * 16;
    int brow = lr + (g >> 1) * 8;
    uint32_t xmB = (uint32_t)lr * 16;
    uint32_t kbB = (uint32_t)(g & 1) * 16;

    float acc[2][8][4] = {};

    for (int kc = 0; kc < 2; kc++) {
        for (int idx = tid; idx < 4096; idx += 256) {
            int r = idx >> 5, kp = idx & 31;
            float2 v = make_float2(0.f, 0.f);
            if (v0 + r < NN) v = *(const float2*)(X + (size_t)(v0 + r) * 128 + kc * 64 + kp * 2);
            uint32_t h2, l2;
            split_pair(v, h2, l2);
            uint32_t o = swz((uint32_t)r * 128u + (uint32_t)kp * 4u);
            *(uint32_t*)((char*)sAh + o) = h2;
            *(uint32_t*)((char*)sAl + o) = l2;
        }
        __syncthreads();

        for (int h = 0; h < 2; h++) {
            {
                const uint4* bh = (const uint4*)((const char*)g_WB_h + bBase0 + h * 8192 + kc * 16384);
                const uint4* bl = (const uint4*)((const char*)g_WB_l + bBase0 + h * 8192 + kc * 16384);
                for (int i = tid; i < 512; i += 256) {
                    ((uint4*)sBh)[i] = bh[i];
                    ((uint4*)sBl)[i] = bl[i];
                }
            }
            __syncthreads();
#pragma unroll
            for (int ks = 0; ks < 4; ks++) {
                uint32_t kb = ks * 32;
                uint32_t ah[4], al[4];
                ldsm4(ah, aPreH + ((kb + kbA) ^ xmA));
                ldsm4(al, aPreL + ((kb + kbA) ^ xmA));
#pragma unroll
                for (int nt2 = 0; nt2 < 4; nt2++) {
                    int n = nt2 * 16 + brow;
                    uint32_t bo = (uint32_t)n * 128 + ((kb + kbB) ^ xmB);
                    uint32_t bh4[4], bl4[4];
                    ldsm4(bh4, bHb + bo);
                    ldsm4(bl4, bLb + bo);
                    mma16816(acc[h][nt2 * 2],     ah, bh4);
                    mma16816(acc[h][nt2 * 2 + 1], ah, bh4 + 2);
                    mma16816(acc[h][nt2 * 2],     al, bh4);
                    mma16816(acc[h][nt2 * 2 + 1], al, bh4 + 2);
                    mma16816(acc[h][nt2 * 2],     ah, bl4);
                    mma16816(acc[h][nt2 * 2 + 1], ah, bl4 + 2);
                }
            }
            __syncthreads();
        }
    }

    int r0 = v0 + wid * 16 + (lane >> 2);
    int cb = (lane & 3) * 2;
#pragma unroll
    for (int h = 0; h < 2; h++) {
        int outOff = h * 64;
#pragma unroll
        for (int j = 0; j < 8; j++) {
            int col = j * 8 + cb;
            if (r0 < NN)
                *(__half2*)(outB + (size_t)r0 * 128 + outOff + col) =
                    __floats2half2_rn(acc[h][j][0], acc[h][j][1]);
            if (r0 + 8 < NN)
                *(__half2*)(outB + (size_t)(r0 + 8) * 128 + outOff + col) =
                    __floats2half2_rn(acc[h][j][2], acc[h][j][3]);
        }
    }
}

// ---------------- Layer 0: half-warp-per-node fp16 mean-gather + fp16 self + bias + tanh ----------------
__global__ void layer0_k(const float* __restrict__ bp, const float* __restrict__ bn) {
    int v = (blockIdx.x * blockDim.x + threadIdx.x) >> 4;   // half-warp per node
    int lane = threadIdx.x & 15;
    if (v >= NN) return;
    int c4 = lane * 4;
    float4 aP = make_float4(0.f, 0.f, 0.f, 0.f);
    float4 aN = make_float4(0.f, 0.f, 0.f, 0.f);
    int b = g_rp_pos[v], e = g_rp_pos[v + 1];
#pragma unroll 4
    for (int i = b; i < e; i++) {
        int s = g_src_pos[i];
        uint2 raw = *(const uint2*)(g_U0h + (size_t)s * 128 + c4);
        float2 f0 = __half22float2(*(const __half2*)&raw.x);
        float2 f1 = __half22float2(*(const __half2*)&raw.y);
        aP.x += f0.x; aP.y += f0.y; aP.z += f1.x; aP.w += f1.y;
    }
    b = g_rp_neg[v]; e = g_rp_neg[v + 1];
#pragma unroll 4
    for (int i = b; i < e; i++) {
        int s = g_src_neg[i];
        uint2 raw = *(const uint2*)(g_U0h + (size_t)s * 128 + 64 + c4);
        float2 f0 = __half22float2(*(const __half2*)&raw.x);
        float2 f1 = __half22float2(*(const __half2*)&raw.y);
        aN.x += f0.x; aN.y += f0.y; aN.z += f1.x; aN.w += f1.y;
    }
    float ipv = g_inv_pos[v], inv = g_inv_neg[v];
    // fp16 self terms
    uint2 spr = *(const uint2*)(g_U0sh + (size_t)v * 128 + c4);
    uint2 snr = *(const uint2*)(g_U0sh + (size_t)v * 128 + 64 + c4);
    float2 sp0 = __half22float2(*(const __half2*)&spr.x);
    float2 sp1 = __half22float2(*(const __half2*)&spr.y);
    float2 sn0 = __half22float2(*(const __half2*)&snr.x);
    float2 sn1 = __half22float2(*(const __half2*)&snr.y);
    float4 b1 = *(const float4*)(bp + c4);
    float4 b2 = *(const float4*)(bn + c4);
    float4 zp, zn;
    zp.x = tanhf(aP.x * ipv + sp0.x + b1.x); zp.y = tanhf(aP.y * ipv + sp0.y + b1.y);
    zp.z = tanhf(aP.z * ipv + sp1.x + b1.z); zp.w = tanhf(aP.w * ipv + sp1.y + b1.w);
    zn.x = tanhf(aN.x * inv + sn0.x + b2.x); zn.y = tanhf(aN.y * inv + sn0.y + b2.y);
    zn.z = tanhf(aN.z * inv + sn1.x + b2.z); zn.w = tanhf(aN.w * inv + sn1.y + b2.w);
    __half2 h0 = __floats2half2_rn(zp.x, zp.y), h1 = __floats2half2_rn(zp.z, zp.w);
    __half2 h2 = __floats2half2_rn(zn.x, zn.y), h3 = __floats2half2_rn(zn.z, zn.w);
    *(uint2*)(g_Zh + (size_t)v * 128 + c4)      = make_uint2(*(uint32_t*)&h0, *(uint32_t*)&h1);
    *(uint2*)(g_Zh + (size_t)v * 128 + 64 + c4) = make_uint2(*(uint32_t*)&h2, *(uint32_t*)&h3);
}

// ---------------- Layer aggregation: half-warp-per-node fp16 gather, permuted fp16 output ----------------
__global__ void agg_k(int zsel) {
    const __half* Z = zsel ? g_Z2h : g_Zh;
    int v = (blockIdx.x * blockDim.x + threadIdx.x) >> 4;   // half-warp per node
    int lane = threadIdx.x & 15;
    if (v >= NN) return;
    int c8 = lane * 8;
    float4 aP0 = make_float4(0.f, 0.f, 0.f, 0.f), aP1 = make_float4(0.f, 0.f, 0.f, 0.f);
    float4 aN0 = make_float4(0.f, 0.f, 0.f, 0.f), aN1 = make_float4(0.f, 0.f, 0.f, 0.f);
    int b = g_rp_pos[v], e = g_rp_pos[v + 1];
#pragma unroll 4
    for (int i = b; i < e; i++) {
        int s = g_src_pos[i];
        uint4 raw = *(const uint4*)(Z + (size_t)s * 128 + c8);
        acc_h8(aP0, aP1, raw);
    }
    b = g_rp_neg[v]; e = g_rp_neg[v + 1];
#pragma unroll 4
    for (int i = b; i < e; i++) {
        int s = g_src_neg[i];
        uint4 raw = *(const uint4*)(Z + (size_t)s * 128 + c8);
        acc_h8(aN0, aN1, raw);
    }
    float ipv = g_inv_pos[v], inv = g_inv_neg[v];
    aP0.x *= ipv; aP0.y *= ipv; aP0.z *= ipv; aP0.w *= ipv;
    aP1.x *= ipv; aP1.y *= ipv; aP1.z *= ipv; aP1.w *= ipv;
    aN0.x *= inv; aN0.y *= inv; aN0.z *= inv; aN0.w *= inv;
    aN1.x *= inv; aN1.y *= inv; aN1.z *= inv; aN1.w *= inv;
    uint4 pP = pack_h8(aP0, aP1);
    uint4 pN = pack_h8(aN0, aN1);
    if (lane < 8) {
        // cols [0,64): Apos -> AGGP[c8], Aneg -> AGGN[64+c8]
        *(uint4*)(g_AGGPh + (size_t)v * 128 + c8)      = pP;
        *(uint4*)(g_AGGNh + (size_t)v * 128 + 64 + c8) = pN;
    } else {
        // cols [64,128): Aneg -> AGGP[c8], Apos -> AGGN[c8-64]
        *(uint4*)(g_AGGPh + (size_t)v * 128 + c8)      = pN;
        *(uint4*)(g_AGGNh + (size_t)v * 128 + c8 - 64) = pP;
    }
}

// ---------------- host launcher (single stream, capture-safe) ----------------
extern "C" void kernel_launch(void* const* d_in, const int* in_sizes, int n_in,
                              void* d_out, int out_size) {
    const float* x = (const float*)d_in[0];
    const int* pe = (const int*)d_in[1];   // int32 (JAX x64 disabled)
    const int* ne = (const int*)d_in[2];
    const float* Wp_l = (const float*)d_in[3];
    const float* Wp_r = (const float*)d_in[4];
    const float* bp = (const float*)d_in[5];
    const float* Wn_l = (const float*)d_in[6];
    const float* Wn_r = (const float*)d_in[7];
    const float* bn = (const float*)d_in[8];
    const float* Wl_pos = (const float*)d_in[9];
    const float* Wr_pos = (const float*)d_in[10];
    const float* b_pos = (const float*)d_in[11];
    const float* Wl_neg = (const float*)d_in[12];
    const float* Wr_neg = (const float*)d_in[13];
    const float* b_neg = (const float*)d_in[14];
    float* out = (float*)d_out;

    __half *dU0h, *dU0sh, *dZh, *dZ2h, *dAGGPh, *dAGGNh;
    cudaGetSymbolAddress((void**)&dU0h, g_U0h);
    cudaGetSymbolAddress((void**)&dU0sh, g_U0sh);
    cudaGetSymbolAddress((void**)&dZh, g_Zh);
    cudaGetSymbolAddress((void**)&dZ2h, g_Z2h);
    cudaGetSymbolAddress((void**)&dAGGPh, g_AGGPh);
    cudaGetSymbolAddress((void**)&dAGGNh, g_AGGNh);

    // --- weight prep ---
    prep_w_k<<<160, 256>>>(Wl_pos, Wr_pos, Wl_neg, Wr_neg, Wp_l, Wn_l, Wp_r, Wn_r);

    // --- CSR build ---
    zero_cnt_k<<<(2 * NN + 255) / 256, 256>>>();
    hist2_k<<<2048, 256>>>(pe + EE, ne + EE);
    const int NB = (NN + 1023) / 1024;
    { dim3 grd(NB, 2); scan1m_k<<<grd, 1024>>>(); }
    scan2m_k<<<2, 128>>>(NB);
    { dim3 grd((NN + 255) / 256, 2); scan3m_k<<<grd, 256>>>(); }
    scatter2_k<<<2048, 256>>>(pe, pe + EE, ne, ne + EE);

    const int NBT = (NN + 127) / 128;       // 782
    const int NBH = (NN * 16 + 255) / 256;  // 6250 (half-warp per node)

    // --- layer 0 ---
    { dim3 grd(NBT, 2); mma_gemm0_dual_k<<<grd, 256>>>(x, dU0h, dU0sh); }
    layer0_k<<<NBH, 256>>>(bp, bn);

    // --- layer 1 ---
    agg_k<<<NBH, 256>>>(0);
    { dim3 grd(NBT, 2); mma_layer_dual_k<<<grd, 256>>>(dAGGPh, dAGGNh, dZh, 0, b_pos, b_neg, nullptr, dZ2h, 1); }

    // --- layer 2 ---
    agg_k<<<NBH, 256>>>(1);
    { dim3 grd(NBT, 2); mma_layer_dual_k<<<grd, 256>>>(dAGGPh, dAGGNh, dZ2h, 2 * 24576, b_pos + 64, b_neg + 64, out, nullptr, 0); }
}

// round 16
// speedup vs baseline: 1.1387x; 1.0667x over previous
#include <cuda_runtime.h>
#include <cuda_fp16.h>
#include <cstdint>

#define NN 100000
#define EE 1200000

// ---------------- device scratch (static, allocation-free) ----------------
__device__ int   g_cnt[2 * NN];
__device__ int   g_rp_pos[NN + 1];
__device__ int   g_rp_neg[NN + 1];
__device__ int   g_cur_pos[NN];
__device__ int   g_cur_neg[NN];
__device__ float g_inv_pos[NN];
__device__ float g_inv_neg[NN];
__device__ int   g_src_pos[EE];
__device__ int   g_src_neg[EE];
__device__ int   g_bsum_pos[128];
__device__ int   g_bsum_neg[128];
__device__ __align__(16) __half g_U0h[NN * 128];   // [yp(64) | yn(64)] fp16 (gathered by layer0)
__device__ __align__(16) __half g_U0sh[NN * 128];  // [sp(64) | sn(64)] fp16 (self terms)
__device__ __align__(16) __half g_Zh[NN * 128];    // z after layer 0 (fp16)
__device__ __align__(16) __half g_Z2h[NN * 128];   // z after layer 1 (fp16)
__device__ __align__(16) __half g_AGGPh[NN * 128]; // [Apos[0:64] | Aneg[64:128]] fp16
__device__ __align__(16) __half g_AGGNh[NN * 128]; // [Apos[64:128] | Aneg[0:64]] fp16

// packed fp16 weights (hi = fp16(W), lo = fp16(W - hi)):
// 4 layer stacks (24576 B each) then gemm0 (2 x 32768 B) = 163840 B
__device__ __align__(16) uint32_t g_WB_h[40960];
__device__ __align__(16) uint32_t g_WB_l[40960];

// ---------------- helpers ----------------
__device__ __forceinline__ uint32_t smem_u32(const void* p) {
    uint32_t a;
    asm("{ .reg .u64 t; cvta.to.shared.u64 t, %1; cvt.u32.u64 %0, t; }" : "=r"(a) : "l"(p));
    return a;
}
__device__ __forceinline__ uint32_t swz(uint32_t o) { return o ^ ((o >> 3) & 0x70); }

// fp16 two-term split of an fp32 pair: hi = fp16(v), lo = fp16(v - hi)
__device__ __forceinline__ void split_pair_f16(float2 v, uint32_t& h2, uint32_t& l2) {
    __half2 h = __floats2half2_rn(v.x, v.y);
    float2 hf = __half22float2(h);
    __half2 l = __floats2half2_rn(v.x - hf.x, v.y - hf.y);
    h2 = *(uint32_t*)&h;
    l2 = *(uint32_t*)&l;
}

__device__ __forceinline__ void ldsm4(uint32_t* r, uint32_t addr) {
    asm volatile("ldmatrix.sync.aligned.m8n8.x4.shared.b16 {%0,%1,%2,%3}, [%4];"
                 : "=r"(r[0]), "=r"(r[1]), "=r"(r[2]), "=r"(r[3]) : "r"(addr));
}

// f16 MMA (A, B fp16; C fp32)
__device__ __forceinline__ void mma16816h(float* c, const uint32_t* a, const uint32_t* b) {
    asm volatile(
        "mma.sync.aligned.m16n8k16.row.col.f32.f16.f16.f32 "
        "{%0,%1,%2,%3}, {%4,%5,%6,%7}, {%8,%9}, {%0,%1,%2,%3};"
        : "+f"(c[0]), "+f"(c[1]), "+f"(c[2]), "+f"(c[3])
        : "r"(a[0]), "r"(a[1]), "r"(a[2]), "r"(a[3]), "r"(b[0]), "r"(b[1]));
}

__device__ __forceinline__ void acc_h8(float4& a0, float4& a1, uint4 raw) {
    float2 f0 = __half22float2(*(const __half2*)&raw.x);
    float2 f1 = __half22float2(*(const __half2*)&raw.y);
    float2 f2 = __half22float2(*(const __half2*)&raw.z);
    float2 f3 = __half22float2(*(const __half2*)&raw.w);
    a0.x += f0.x; a0.y += f0.y; a0.z += f1.x; a0.w += f1.y;
    a1.x += f2.x; a1.y += f2.y; a1.z += f3.x; a1.w += f3.y;
}

__device__ __forceinline__ uint4 pack_h8(float4 a0, float4 a1) {
    __half2 h0 = __floats2half2_rn(a0.x, a0.y), h1 = __floats2half2_rn(a0.z, a0.w);
    __half2 h2 = __floats2half2_rn(a1.x, a1.y), h3 = __floats2half2_rn(a1.z, a1.w);
    return make_uint4(*(uint32_t*)&h0, *(uint32_t*)&h1, *(uint32_t*)&h2, *(uint32_t*)&h3);
}

// ---------------- CSR build ----------------
__global__ void zero_cnt_k() {
    int i = blockIdx.x * blockDim.x + threadIdx.x;
    if (i < 2 * NN) g_cnt[i] = 0;
}
__global__ void hist2_k(const int* __restrict__ pdst, const int* __restrict__ ndst) {
    for (int i = blockIdx.x * blockDim.x + threadIdx.x; i < 2 * EE; i += gridDim.x * blockDim.x) {
        if (i < EE) atomicAdd(&g_cnt[pdst[i]], 1);
        else        atomicAdd(&g_cnt[NN + ndst[i - EE]], 1);
    }
}
__global__ void scan1m_k() {
    int which = blockIdx.y;
    const int* cnt = g_cnt + which * NN;
    int* incl = which ? g_rp_neg : g_rp_pos;
    int* bsum = which ? g_bsum_neg : g_bsum_pos;
    __shared__ int sh[1024];
    int i = blockIdx.x * 1024 + threadIdx.x;
    int v = (i < NN) ? cnt[i] : 0;
    sh[threadIdx.x] = v;
    __syncthreads();
    for (int off = 1; off < 1024; off <<= 1) {
        int t = (threadIdx.x >= off) ? sh[threadIdx.x - off] : 0;
        __syncthreads();
        sh[threadIdx.x] += t;
        __syncthreads();
    }
    if (i < NN) incl[i] = sh[threadIdx.x];
    if (threadIdx.x == 1023) bsum[blockIdx.x] = sh[1023];
}
__global__ void scan2m_k(int nb) {
    int which = blockIdx.x;
    int* bsum = which ? g_bsum_neg : g_bsum_pos;
    __shared__ int sh[128];
    int v = (threadIdx.x < nb) ? bsum[threadIdx.x] : 0;
    sh[threadIdx.x] = v;
    __syncthreads();
    for (int off = 1; off < 128; off <<= 1) {
        int t = (threadIdx.x >= off) ? sh[threadIdx.x - off] : 0;
        __syncthreads();
        sh[threadIdx.x] += t;
        __syncthreads();
    }
    if (threadIdx.x < nb) bsum[threadIdx.x] = sh[threadIdx.x] - v;
}
__global__ void scan3m_k() {
    int which = blockIdx.y;
    const int* cnt = g_cnt + which * NN;
    int* rp = which ? g_rp_neg : g_rp_pos;
    int* cur = which ? g_cur_neg : g_cur_pos;
    float* inv = which ? g_inv_neg : g_inv_pos;
    const int* bsum = which ? g_bsum_neg : g_bsum_pos;
    int i = blockIdx.x * blockDim.x + threadIdx.x;
    if (i < NN) {
        int inc = rp[i] + bsum[i >> 10];
        int c = cnt[i];
        int ex = inc - c;
        rp[i] = ex;
        cur[i] = ex;
        inv[i] = 1.0f / (float)(c > 0 ? c : 1);
    }
    if (i == 0) rp[NN] = EE;
}
__global__ void scatter2_k(const int* __restrict__ ps, const int* __restrict__ pd,
                           const int* __restrict__ ns, const int* __restrict__ nd) {
    for (int i = blockIdx.x * blockDim.x + threadIdx.x; i < 2 * EE; i += gridDim.x * blockDim.x) {
        if (i < EE) {
            int d = pd[i];
            int p = atomicAdd(&g_cur_pos[d], 1);
            g_src_pos[p] = ps[i];
        } else {
            int d = nd[i - EE];
            int p = atomicAdd(&g_cur_neg[d], 1);
            g_src_neg[p] = ns[i - EE];
        }
    }
}

// ---------------- weight prep: fp32 -> fp16 hi/lo, [n][k] rows, SW128-swizzled 64-k chunks ----------------
__global__ void prep_w_k(const float* __restrict__ Wl_pos, const float* __restrict__ Wr_pos,
                         const float* __restrict__ Wl_neg, const float* __restrict__ Wr_neg,
                         const float* __restrict__ Wp_l, const float* __restrict__ Wn_l,
                         const float* __restrict__ Wp_r, const float* __restrict__ Wn_r) {
    int idx = blockIdx.x * blockDim.x + threadIdx.x;
    float2 v;
    uint32_t off;
    if (idx < 24576) {
        int stack = idx / 6144, rem = idx % 6144;
        int n = rem / 96, kp = rem % 96, k = kp * 2;
        int l = stack >> 1, h = stack & 1;
        const float* WL = h ? Wl_neg : Wl_pos;  // [2][128][64]
        const float* WR = h ? Wr_neg : Wr_pos;  // [2][64][64]
        if (k < 128) {
            v.x = WL[l * 8192 + k * 64 + n];
            v.y = WL[l * 8192 + (k + 1) * 64 + n];
        } else {
            int kk = k - 128;
            v.x = WR[l * 4096 + kk * 64 + n];
            v.y = WR[l * 4096 + (kk + 1) * 64 + n];
        }
        off = (uint32_t)stack * 24576u + (uint32_t)(k >> 6) * 8192u + swz((uint32_t)n * 128u + (k & 63) * 2u);
    } else if (idx < 24576 + 16384) {
        int j = idx - 24576;
        int colsel = j / 8192, rem = j % 8192;
        int n = rem / 64, kp = rem % 64, k = kp * 2;
        const float* W = (n < 64) ? (colsel ? Wp_r : Wp_l) : (colsel ? Wn_r : Wn_l);
        int nn = n & 63;
        v.x = W[k * 64 + nn];
        v.y = W[(k + 1) * 64 + nn];
        off = 98304u + (uint32_t)colsel * 32768u + (uint32_t)(k >> 6) * 16384u + swz((uint32_t)n * 128u + (k & 63) * 2u);
    } else {
        return;
    }
    uint32_t h2, l2;
    split_pair_f16(v, h2, l2);
    g_WB_h[off >> 2] = h2;
    g_WB_l[off >> 2] = l2;
}

// ---------------- layer GEMM, both halves in one launch (blockIdx.y = half); fp16 A direct ----------------
// out_half = act([AGGh | z_half] @ [Wl;Wr] + b); C = A@Wh + A@Wl (W fp16 two-term).
__global__ void __launch_bounds__(256) mma_layer_dual_k(
    const __half* __restrict__ A0a, const __half* __restrict__ A0b,
    const __half* __restrict__ A1h, int bBaseA,
    const float* __restrict__ biasA, const float* __restrict__ biasB,
    float* __restrict__ outF, __half* __restrict__ outH, int outHalf)
{
    __shared__ uint32_t sA[4096];               // 128 rows x 64 fp16 (16 KB)
    __shared__ uint32_t sBh[2048], sBl[2048];   // 64 rows x 64 fp16 each (8 KB each)
    int tid = threadIdx.x, wid = tid >> 5, lane = tid & 31;
    int v0 = blockIdx.x * 128;
    int h = blockIdx.y;
    const __half* A0 = h ? A0b : A0a;
    const float* bias = h ? biasB : biasA;
    int bBase = bBaseA + h * 24576;
    int zOff = h * 64, outOff = h * 64;

    uint32_t aB = smem_u32(sA);
    uint32_t bHb = smem_u32(sBh), bLb = smem_u32(sBl);

    int lr = lane & 7, g = lane >> 3;
    int arow = wid * 16 + lr + (g & 1) * 8;
    uint32_t aPre = aB + arow * 128;
    uint32_t xmA = (uint32_t)(arow & 7) * 16;
    uint32_t kbA = (uint32_t)(g >> 1) * 16;
    int brow = lr + (g >> 1) * 8;
    uint32_t xmB = (uint32_t)lr * 16;
    uint32_t kbB = (uint32_t)(g & 1) * 16;

    float acc[8][4] = {};

    for (int kc = 0; kc < 3; kc++) {
        {
            const uint4* bh = (const uint4*)((const char*)g_WB_h + bBase + kc * 8192);
            const uint4* bl = (const uint4*)((const char*)g_WB_l + bBase + kc * 8192);
            for (int i = tid; i < 512; i += 256) {
                ((uint4*)sBh)[i] = bh[i];
                ((uint4*)sBl)[i] = bl[i];
            }
        }
        // A staging: raw fp16 copy, swizzled
        for (int idx = tid; idx < 4096; idx += 256) {
            int r = idx >> 5, kp = idx & 31;
            uint32_t w = 0;
            if (v0 + r < NN) {
                const __half* src = (kc == 2) ? (A1h + (size_t)(v0 + r) * 128 + zOff + kp * 2)
                                              : (A0 + (size_t)(v0 + r) * 128 + kc * 64 + kp * 2);
                w = *(const uint32_t*)src;
            }
            *(uint32_t*)((char*)sA + swz((uint32_t)r * 128u + (uint32_t)kp * 4u)) = w;
        }
        __syncthreads();

#pragma unroll
        for (int ks = 0; ks < 4; ks++) {
            uint32_t kb = ks * 32;
            uint32_t a4[4];
            ldsm4(a4, aPre + ((kb + kbA) ^ xmA));
#pragma unroll
            for (int nt2 = 0; nt2 < 4; nt2++) {
                int n = nt2 * 16 + brow;
                uint32_t bo = (uint32_t)n * 128 + ((kb + kbB) ^ xmB);
                uint32_t bh4[4], bl4[4];
                ldsm4(bh4, bHb + bo);
                ldsm4(bl4, bLb + bo);
                mma16816h(acc[nt2 * 2],     a4, bh4);
                mma16816h(acc[nt2 * 2 + 1], a4, bh4 + 2);
                mma16816h(acc[nt2 * 2],     a4, bl4);
                mma16816h(acc[nt2 * 2 + 1], a4, bl4 + 2);
            }
        }
        __syncthreads();
    }

    int r0 = v0 + wid * 16 + (lane >> 2);
    int cb = (lane & 3) * 2;
#pragma unroll
    for (int j = 0; j < 8; j++) {
        int col = j * 8 + cb;
        float bx = bias[col], by = bias[col + 1];
        float ox = tanhf(acc[j][0] + bx), oy = tanhf(acc[j][1] + by);
        float px = tanhf(acc[j][2] + bx), py = tanhf(acc[j][3] + by);
        if (outHalf) {
            if (r0 < NN)     *(__half2*)(outH + (size_t)r0 * 128 + outOff + col)       = __floats2half2_rn(ox, oy);
            if (r0 + 8 < NN) *(__half2*)(outH + (size_t)(r0 + 8) * 128 + outOff + col) = __floats2half2_rn(px, py);
        } else {
            if (r0 < NN)     *(float2*)(outF + (size_t)r0 * 128 + outOff + col)       = make_float2(ox, oy);
            if (r0 + 8 < NN) *(float2*)(outF + (size_t)(r0 + 8) * 128 + outOff + col) = make_float2(px, py);
        }
    }
}

// ---------------- fused layer-0 GEMM: stage X once (fp16), both 64-col halves; blockIdx.y = colsel ----------------
__global__ void __launch_bounds__(256) mma_gemm0_dual_k(
    const float* __restrict__ X,
    __half* __restrict__ outL, __half* __restrict__ outR)
{
    __shared__ uint32_t sA[4096];
    __shared__ uint32_t sBh[2048], sBl[2048];
    int tid = threadIdx.x, wid = tid >> 5, lane = tid & 31;
    int v0 = blockIdx.x * 128;
    int colsel = blockIdx.y;                  // 0 = left weights -> U0h, 1 = right -> U0sh
    int bBase0 = 98304 + colsel * 32768;
    __half* outB = colsel ? outR : outL;

    uint32_t aB = smem_u32(sA);
    uint32_t bHb = smem_u32(sBh), bLb = smem_u32(sBl);

    int lr = lane & 7, g = lane >> 3;
    int arow = wid * 16 + lr + (g & 1) * 8;
    uint32_t aPre = aB + arow * 128;
    uint32_t xmA = (uint32_t)(arow & 7) * 16;
    uint32_t kbA = (uint32_t)(g >> 1) * 16;
    int brow = lr + (g >> 1) * 8;
    uint32_t xmB = (uint32_t)lr * 16;
    uint32_t kbB = (uint32_t)(g & 1) * 16;

    float acc[2][8][4] = {};

    for (int kc = 0; kc < 2; kc++) {
        // stage A = fp16(X chunk)
        for (int idx = tid; idx < 4096; idx += 256) {
            int r = idx >> 5, kp = idx & 31;
            uint32_t w = 0;
            if (v0 + r < NN) {
                float2 v = *(const float2*)(X + (size_t)(v0 + r) * 128 + kc * 64 + kp * 2);
                __half2 hh = __floats2half2_rn(v.x, v.y);
                w = *(uint32_t*)&hh;
            }
            *(uint32_t*)((char*)sA + swz((uint32_t)r * 128u + (uint32_t)kp * 4u)) = w;
        }
        __syncthreads();

        for (int h = 0; h < 2; h++) {
            {
                const uint4* bh = (const uint4*)((const char*)g_WB_h + bBase0 + h * 8192 + kc * 16384);
                const uint4* bl = (const uint4*)((const char*)g_WB_l + bBase0 + h * 8192 + kc * 16384);
                for (int i = tid; i < 512; i += 256) {
                    ((uint4*)sBh)[i] = bh[i];
                    ((uint4*)sBl)[i] = bl[i];
                }
            }
            __syncthreads();
#pragma unroll
            for (int ks = 0; ks < 4; ks++) {
                uint32_t kb = ks * 32;
                uint32_t a4[4];
                ldsm4(a4, aPre + ((kb + kbA) ^ xmA));
#pragma unroll
                for (int nt2 = 0; nt2 < 4; nt2++) {
                    int n = nt2 * 16 + brow;
                    uint32_t bo = (uint32_t)n * 128 + ((kb + kbB) ^ xmB);
                    uint32_t bh4[4], bl4[4];
                    ldsm4(bh4, bHb + bo);
                    ldsm4(bl4, bLb + bo);
                    mma16816h(acc[h][nt2 * 2],     a4, bh4);
                    mma16816h(acc[h][nt2 * 2 + 1], a4, bh4 + 2);
                    mma16816h(acc[h][nt2 * 2],     a4, bl4);
                    mma16816h(acc[h][nt2 * 2 + 1], a4, bl4 + 2);
                }
            }
            __syncthreads();
        }
    }

    int r0 = v0 + wid * 16 + (lane >> 2);
    int cb = (lane & 3) * 2;
#pragma unroll
    for (int h = 0; h < 2; h++) {
        int outOff = h * 64;
#pragma unroll
        for (int j = 0; j < 8; j++) {
            int col = j * 8 + cb;
            if (r0 < NN)
                *(__half2*)(outB + (size_t)r0 * 128 + outOff + col) =
                    __floats2half2_rn(acc[h][j][0], acc[h][j][1]);
            if (r0 + 8 < NN)
                *(__half2*)(outB + (size_t)(r0 + 8) * 128 + outOff + col) =
                    __floats2half2_rn(acc[h][j][2], acc[h][j][3]);
        }
    }
}

// ---------------- Layer 0: half-warp-per-node fp16 mean-gather + fp16 self + bias + tanh ----------------
__global__ void layer0_k(const float* __restrict__ bp, const float* __restrict__ bn) {
    int v = (blockIdx.x * blockDim.x + threadIdx.x) >> 4;   // half-warp per node
    int lane = threadIdx.x & 15;
    if (v >= NN) return;
    int c4 = lane * 4;
    float4 aP = make_float4(0.f, 0.f, 0.f, 0.f);
    float4 aN = make_float4(0.f, 0.f, 0.f, 0.f);
    int b = g_rp_pos[v], e = g_rp_pos[v + 1];
#pragma unroll 4
    for (int i = b; i < e; i++) {
        int s = g_src_pos[i];
        uint2 raw = *(const uint2*)(g_U0h + (size_t)s * 128 + c4);
        float2 f0 = __half22float2(*(const __half2*)&raw.x);
        float2 f1 = __half22float2(*(const __half2*)&raw.y);
        aP.x += f0.x; aP.y += f0.y; aP.z += f1.x; aP.w += f1.y;
    }
    b = g_rp_neg[v]; e = g_rp_neg[v + 1];
#pragma unroll 4
    for (int i = b; i < e; i++) {
        int s = g_src_neg[i];
        uint2 raw = *(const uint2*)(g_U0h + (size_t)s * 128 + 64 + c4);
        float2 f0 = __half22float2(*(const __half2*)&raw.x);
        float2 f1 = __half22float2(*(const __half2*)&raw.y);
        aN.x += f0.x; aN.y += f0.y; aN.z += f1.x; aN.w += f1.y;
    }
    float ipv = g_inv_pos[v], inv = g_inv_neg[v];
    uint2 spr = *(const uint2*)(g_U0sh + (size_t)v * 128 + c4);
    uint2 snr = *(const uint2*)(g_U0sh + (size_t)v * 128 + 64 + c4);
    float2 sp0 = __half22float2(*(const __half2*)&spr.x);
    float2 sp1 = __half22float2(*(const __half2*)&spr.y);
    float2 sn0 = __half22float2(*(const __half2*)&snr.x);
    float2 sn1 = __half22float2(*(const __half2*)&snr.y);
    float4 b1 = *(const float4*)(bp + c4);
    float4 b2 = *(const float4*)(bn + c4);
    float4 zp, zn;
    zp.x = tanhf(aP.x * ipv + sp0.x + b1.x); zp.y = tanhf(aP.y * ipv + sp0.y + b1.y);
    zp.z = tanhf(aP.z * ipv + sp1.x + b1.z); zp.w = tanhf(aP.w * ipv + sp1.y + b1.w);
    zn.x = tanhf(aN.x * inv + sn0.x + b2.x); zn.y = tanhf(aN.y * inv + sn0.y + b2.y);
    zn.z = tanhf(aN.z * inv + sn1.x + b2.z); zn.w = tanhf(aN.w * inv + sn1.y + b2.w);
    __half2 h0 = __floats2half2_rn(zp.x, zp.y), h1 = __floats2half2_rn(zp.z, zp.w);
    __half2 h2 = __floats2half2_rn(zn.x, zn.y), h3 = __floats2half2_rn(zn.z, zn.w);
    *(uint2*)(g_Zh + (size_t)v * 128 + c4)      = make_uint2(*(uint32_t*)&h0, *(uint32_t*)&h1);
    *(uint2*)(g_Zh + (size_t)v * 128 + 64 + c4) = make_uint2(*(uint32_t*)&h2, *(uint32_t*)&h3);
}

// ---------------- Layer aggregation: half-warp-per-node fp16 gather, permuted fp16 output ----------------
__global__ void agg_k(int zsel) {
    const __half* Z = zsel ? g_Z2h : g_Zh;
    int v = (blockIdx.x * blockDim.x + threadIdx.x) >> 4;   // half-warp per node
    int lane = threadIdx.x & 15;
    if (v >= NN) return;
    int c8 = lane * 8;
    float4 aP0 = make_float4(0.f, 0.f, 0.f, 0.f), aP1 = make_float4(0.f, 0.f, 0.f, 0.f);
    float4 aN0 = make_float4(0.f, 0.f, 0.f, 0.f), aN1 = make_float4(0.f, 0.f, 0.f, 0.f);
    int b = g_rp_pos[v], e = g_rp_pos[v + 1];
#pragma unroll 4
    for (int i = b; i < e; i++) {
        int s = g_src_pos[i];
        uint4 raw = *(const uint4*)(Z + (size_t)s * 128 + c8);
        acc_h8(aP0, aP1, raw);
    }
    b = g_rp_neg[v]; e = g_rp_neg[v + 1];
#pragma unroll 4
    for (int i = b; i < e; i++) {
        int s = g_src_neg[i];
        uint4 raw = *(const uint4*)(Z + (size_t)s * 128 + c8);
        acc_h8(aN0, aN1, raw);
    }
    float ipv = g_inv_pos[v], inv = g_inv_neg[v];
    aP0.x *= ipv; aP0.y *= ipv; aP0.z *= ipv; aP0.w *= ipv;
    aP1.x *= ipv; aP1.y *= ipv; aP1.z *= ipv; aP1.w *= ipv;
    aN0.x *= inv; aN0.y *= inv; aN0.z *= inv; aN0.w *= inv;
    aN1.x *= inv; aN1.y *= inv; aN1.z *= inv; aN1.w *= inv;
    uint4 pP = pack_h8(aP0, aP1);
    uint4 pN = pack_h8(aN0, aN1);
    if (lane < 8) {
        *(uint4*)(g_AGGPh + (size_t)v * 128 + c8)      = pP;
        *(uint4*)(g_AGGNh + (size_t)v * 128 + 64 + c8) = pN;
    } else {
        *(uint4*)(g_AGGPh + (size_t)v * 128 + c8)      = pN;
        *(uint4*)(g_AGGNh + (size_t)v * 128 + c8 - 64) = pP;
    }
}

// ---------------- host launcher (single stream, capture-safe) ----------------
extern "C" void kernel_launch(void* const* d_in, const int* in_sizes, int n_in,
                              void* d_out, int out_size) {
    const float* x = (const float*)d_in[0];
    const int* pe = (const int*)d_in[1];   // int32 (JAX x64 disabled)
    const int* ne = (const int*)d_in[2];
    const float* Wp_l = (const float*)d_in[3];
    const float* Wp_r = (const float*)d_in[4];
    const float* bp = (const float*)d_in[5];
    const float* Wn_l = (const float*)d_in[6];
    const float* Wn_r = (const float*)d_in[7];
    const float* bn = (const float*)d_in[8];
    const float* Wl_pos = (const float*)d_in[9];
    const float* Wr_pos = (const float*)d_in[10];
    const float* b_pos = (const float*)d_in[11];
    const float* Wl_neg = (const float*)d_in[12];
    const float* Wr_neg = (const float*)d_in[13];
    const float* b_neg = (const float*)d_in[14];
    float* out = (float*)d_out;

    __half *dU0h, *dU0sh, *dZh, *dZ2h, *dAGGPh, *dAGGNh;
    cudaGetSymbolAddress((void**)&dU0h, g_U0h);
    cudaGetSymbolAddress((void**)&dU0sh, g_U0sh);
    cudaGetSymbolAddress((void**)&dZh, g_Zh);
    cudaGetSymbolAddress((void**)&dZ2h, g_Z2h);
    cudaGetSymbolAddress((void**)&dAGGPh, g_AGGPh);
    cudaGetSymbolAddress((void**)&dAGGNh, g_AGGNh);

    // --- weight prep ---
    prep_w_k<<<160, 256>>>(Wl_pos, Wr_pos, Wl_neg, Wr_neg, Wp_l, Wn_l, Wp_r, Wn_r);

    // --- CSR build ---
    zero_cnt_k<<<(2 * NN + 255) / 256, 256>>>();
    hist2_k<<<2048, 256>>>(pe + EE, ne + EE);
    const int NB = (NN + 1023) / 1024;
    { dim3 grd(NB, 2); scan1m_k<<<grd, 1024>>>(); }
    scan2m_k<<<2, 128>>>(NB);
    { dim3 grd((NN + 255) / 256, 2); scan3m_k<<<grd, 256>>>(); }
    scatter2_k<<<2048, 256>>>(pe, pe + EE, ne, ne + EE);

    const int NBT = (NN + 127) / 128;       // 782
    const int NBH = (NN * 16 + 255) / 256;  // 6250 (half-warp per node)

    // --- layer 0 ---
    { dim3 grd(NBT, 2); mma_gemm0_dual_k<<<grd, 256>>>(x, dU0h, dU0sh); }
    layer0_k<<<NBH, 256>>>(bp, bn);

    // --- layer 1 ---
    agg_k<<<NBH, 256>>>(0);
    { dim3 grd(NBT, 2); mma_layer_dual_k<<<grd, 256>>>(dAGGPh, dAGGNh, dZh, 0, b_pos, b_neg, nullptr, dZ2h, 1); }

    // --- layer 2 ---
    agg_k<<<NBH, 256>>>(1);
    { dim3 grd(NBT, 2); mma_layer_dual_k<<<grd, 256>>>(dAGGPh, dAGGNh, dZ2h, 2 * 24576, b_pos + 64, b_neg + 64, out, nullptr, 0); }
}